// round 15
// baseline (speedup 1.0000x reference)
#include <cuda_runtime.h>

#define FULL 0xFFFFFFFFu
typedef unsigned long long u64;

__device__ float g_partials[256];
__device__ unsigned int g_cnt = 0;

__device__ __forceinline__ u64 pk(float lo, float hi) {
    u64 d; asm("mov.b64 %0, {%1, %2};" : "=l"(d) : "f"(lo), "f"(hi)); return d;
}
__device__ __forceinline__ float lo2(u64 d) { return __uint_as_float((unsigned)d); }
__device__ __forceinline__ float hi2(u64 d) { return __uint_as_float((unsigned)(d >> 32)); }
__device__ __forceinline__ u64 fma2(u64 a, u64 b, u64 c) {
    u64 d; asm("fma.rn.f32x2 %0, %1, %2, %3;" : "=l"(d) : "l"(a), "l"(b), "l"(c)); return d;
}
__device__ __forceinline__ u64 mul2(u64 a, u64 b) {
    u64 d; asm("mul.rn.f32x2 %0, %1, %2;" : "=l"(d) : "l"(a), "l"(b)); return d;
}

// Two contexts per warp (each: 2 batches in 16-lane segments, 4 states/lane,
// R12 machinery). STEP2 interleaves the contexts statement-by-statement so
// each context's shfl latency is hidden by the other's arithmetic.
struct Ctx {
    u64 tM2M01, tM2M23, tI2M01, tI2M23;
    u64 tqI2I01, tqI2I23, tqM2I01, tqM2I23;
    u64 cc01, cc23, dd01, dd23;
    float t64M2M, tq64M2I, t64I2M, tq64I2I, t64D2M, P_B;
    unsigned sE4a;
    const float* sECw;
    const int* sxw;
    u64 FM01, FM23, FI01, FI23, w01, w23, PRE01, PRE23;
    float FM64, FI64, incl, S;
};

__global__ void __launch_bounds__(128)
phmm_kernel(const int* __restrict__ xin, const float* __restrict__ trans,
            const float* __restrict__ emis, const float* __restrict__ mus,
            const float* __restrict__ logvars, float* __restrict__ out)
{
    const int lane = threadIdx.x & 31;
    const int sl   = lane & 15;
    const int seg  = lane >> 4;
    const int warp = threadIdx.x >> 5;

    __shared__ float4 sE4[8 * 4 * 32];
    __shared__ float  sEC[8 * 4 * 32];
    __shared__ int    sx[16 * 132];
    __shared__ float  sred[16];
    __shared__ int    sflag;
    __shared__ float  s2[128];

    const float mk1 = (sl >= 1) ? 1.0f : 0.0f;
    const float mk2 = (sl >= 2) ? 1.0f : 0.0f;
    const float mk4 = (sl >= 4) ? 1.0f : 0.0f;
    const float mk8 = (sl >= 8) ? 1.0f : 0.0f;

    Ctx c0, c1;

    #pragma unroll
    for (int ctx = 0; ctx < 2; ctx++) {
        Ctx& c = ctx ? c1 : c0;
        const int b = blockIdx.x * 16 + warp * 4 + ctx * 2 + seg;

        c.sxw = &sx[(warp * 4 + ctx * 2 + seg) * 132];
        {
            const int* xb = xin + b * 128;
            int* sw = (int*)c.sxw;
            #pragma unroll
            for (int i = 0; i < 8; i++) sw[sl + 16 * i] = xb[sl + 16 * i];
        }

        const float* ab = trans + b * 455;
        const float* a0 = ab + 28 * sl;
        float tM2M[4], tqM2I[4], tI2M[4], tqI2I[4], tM2D[4], tD2M[4], tD2D[4];
        #pragma unroll
        for (int j = 0; j < 4; j++) {
            tM2M[j]  = __expf(a0[7 * j + 0]);
            tqM2I[j] = 0.25f * __expf(a0[7 * j + 1]);
            tM2D[j]  = __expf(a0[7 * j + 2]);
            tI2M[j]  = __expf(a0[7 * j + 3]);
            tqI2I[j] = 0.25f * __expf(a0[7 * j + 4]);
            tD2M[j]  = __expf(a0[7 * j + 5]);
            tD2D[j]  = __expf(a0[7 * j + 6]);
        }
        const float* a64 = ab + 64 * 7;
        c.t64M2M  = __expf(a64[0]);
        c.tq64M2I = 0.25f * __expf(a64[1]);
        c.t64I2M  = __expf(a64[3]);
        c.tq64I2I = 0.25f * __expf(a64[4]);
        c.t64D2M  = __expf(a64[5]);

        const float* eb = emis + b * 256;
        #pragma unroll
        for (int x = 0; x < 4; x++) {
            float4 v;
            v.x = (sl == 0) ? 0.0f : __expf(eb[(4 * sl - 1) * 4 + x]);
            v.y = __expf(eb[(4 * sl + 0) * 4 + x]);
            v.z = __expf(eb[(4 * sl + 1) * 4 + x]);
            v.w = __expf(eb[(4 * sl + 2) * 4 + x]);
            int idx = ((warp * 2 + ctx) * 4 + x) * 32 + lane;
            sE4[idx] = v;
            sEC[idx] = __expf(eb[63 * 4 + x]);
        }

        {
            float q0 = tD2D[0], q01 = q0 * tD2D[1];
            float q012 = q01 * tD2D[2], q0123 = q012 * tD2D[3];
            float Q = q0123;
            #pragma unroll
            for (int off = 1; off < 16; off <<= 1) {
                float q = __shfl_up_sync(FULL, Q, off, 16);
                if (sl >= off) Q *= q;
            }
            float Pex = __shfl_up_sync(FULL, Q, 1, 16);
            if (sl == 0) Pex = 1.0f;
            float Pa = Pex * q0, Pb = Pex * q01, Pc = Pex * q012, Pd = Pex * q0123;
            c.dd01 = pk(tD2M[0] * Pex, tD2M[1] * Pa);
            c.dd23 = pk(tD2M[2] * Pb,  tD2M[3] * Pc);
            c.cc01 = pk(__fdividef(tM2D[0], Pa), __fdividef(tM2D[1], Pb));
            c.cc23 = pk(__fdividef(tM2D[2], Pc), __fdividef(tM2D[3], Pd));
            c.P_B = Q;
        }
        c.tM2M01  = pk(tM2M[0], tM2M[1]);   c.tM2M23  = pk(tM2M[2], tM2M[3]);
        c.tI2M01  = pk(tI2M[0], tI2M[1]);   c.tI2M23  = pk(tI2M[2], tI2M[3]);
        c.tqI2I01 = pk(tqI2I[0], tqI2I[1]); c.tqI2I23 = pk(tqI2I[2], tqI2I[3]);
        c.tqM2I01 = pk(tqM2I[0], tqM2I[1]); c.tqM2I23 = pk(tqM2I[2], tqM2I[3]);

        c.sE4a = (unsigned)__cvta_generic_to_shared(&sE4[(warp * 2 + ctx) * 128 + lane]);
        c.sECw = &sEC[(warp * 2 + ctx) * 128 + lane];

        c.FM01 = pk((sl == 0) ? 1.0f : 0.0f, 0.0f);
        c.FM23 = pk(0.0f, 0.0f);
        c.FI01 = pk(0.0f, 0.0f); c.FI23 = pk(0.0f, 0.0f);
        c.FM64 = 0.0f; c.FI64 = 0.0f; c.S = 0.0f;
    }
    __syncwarp();

#define DCHAIN(c)                                                             \
    {                                                                         \
        u64 u01 = mul2(c.cc01, c.FM01);                                       \
        u64 u23 = mul2(c.cc23, c.FM23);                                       \
        float u0 = lo2(u01), u1 = hi2(u01), u2 = lo2(u23), u3 = hi2(u23);     \
        float s0 = u0, s1 = s0 + u1, s2 = s1 + u2, s3 = s2 + u3;              \
        float T = s3;                                                         \
        float t1 = __shfl_up_sync(FULL, T, 1, 16);  T = fmaf(mk1, t1, T);     \
        float t2 = __shfl_up_sync(FULL, T, 2, 16);  T = fmaf(mk2, t2, T);     \
        float t4 = __shfl_up_sync(FULL, T, 4, 16);  T = fmaf(mk4, t4, T);     \
        float t8 = __shfl_up_sync(FULL, T, 8, 16);  T = fmaf(mk8, t8, T);     \
        c.incl = T;                                                           \
        float ex = T - s3;                                                    \
        c.w01 = pk(ex, ex + s0);                                              \
        c.w23 = pk(ex + s1, ex + s2);                                         \
    }

    // Fully interleaved double-step: both contexts advance one timestep.
#define STEP2(XS0, XS1)                                                       \
    {                                                                         \
        u64 a_ev01, a_ev23, b_ev01, b_ev23;                                   \
        asm("ld.shared.v2.u64 {%0, %1}, [%2];"                                \
            : "=l"(a_ev01), "=l"(a_ev23) : "r"(c0.sE4a + (unsigned)(XS0) * 512)); \
        asm("ld.shared.v2.u64 {%0, %1}, [%2];"                                \
            : "=l"(b_ev01), "=l"(b_ev23) : "r"(c1.sE4a + (unsigned)(XS1) * 512)); \
        float a_eC = c0.sECw[(XS0) * 32];                                     \
        float b_eC = c1.sECw[(XS1) * 32];                                     \
        u64 a_p01 = fma2(c0.dd01, c0.w01, c0.PRE01);                          \
        u64 a_p23 = fma2(c0.dd23, c0.w23, c0.PRE23);                          \
        u64 b_p01 = fma2(c1.dd01, c1.w01, c1.PRE01);                          \
        u64 b_p23 = fma2(c1.dd23, c1.w23, c1.PRE23);                          \
        float a_p3 = hi2(a_p23), b_p3 = hi2(b_p23);                           \
        float a_pUp = __shfl_up_sync(FULL, a_p3, 1, 16);                      \
        float b_pUp = __shfl_up_sync(FULL, b_p3, 1, 16);                      \
        c0.FI01 = fma2(c0.tqI2I01, c0.FI01, mul2(c0.tqM2I01, c0.FM01));       \
        c0.FI23 = fma2(c0.tqI2I23, c0.FI23, mul2(c0.tqM2I23, c0.FM23));       \
        c0.FI64 = fmaf(c0.tq64I2I, c0.FI64, c0.tq64M2I * c0.FM64);            \
        c1.FI01 = fma2(c1.tqI2I01, c1.FI01, mul2(c1.tqM2I01, c1.FM01));       \
        c1.FI23 = fma2(c1.tqI2I23, c1.FI23, mul2(c1.tqM2I23, c1.FM23));       \
        c1.FI64 = fmaf(c1.tq64I2I, c1.FI64, c1.tq64M2I * c1.FM64);            \
        c0.FM01 = mul2(a_ev01, pk(a_pUp, lo2(a_p01)));                        \
        c0.FM23 = mul2(a_ev23, pk(hi2(a_p01), lo2(a_p23)));                   \
        c0.FM64 = a_eC * a_p3;                                                \
        u64 a_u01 = mul2(c0.cc01, c0.FM01);                                   \
        u64 a_u23 = mul2(c0.cc23, c0.FM23);                                   \
        float a_u0 = lo2(a_u01), a_u1 = hi2(a_u01);                           \
        float a_u2 = lo2(a_u23), a_u3 = hi2(a_u23);                           \
        float a_s0 = a_u0, a_s1 = a_s0 + a_u1;                                \
        float a_s2 = a_s1 + a_u2, a_s3 = a_s2 + a_u3;                         \
        float a_T = a_s3;                                                     \
        c1.FM01 = mul2(b_ev01, pk(b_pUp, lo2(b_p01)));                        \
        c1.FM23 = mul2(b_ev23, pk(hi2(b_p01), lo2(b_p23)));                   \
        c1.FM64 = b_eC * b_p3;                                                \
        u64 b_u01 = mul2(c1.cc01, c1.FM01);                                   \
        u64 b_u23 = mul2(c1.cc23, c1.FM23);                                   \
        float b_u0 = lo2(b_u01), b_u1 = hi2(b_u01);                           \
        float b_u2 = lo2(b_u23), b_u3 = hi2(b_u23);                           \
        float b_s0 = b_u0, b_s1 = b_s0 + b_u1;                                \
        float b_s2 = b_s1 + b_u2, b_s3 = b_s2 + b_u3;                         \
        float b_T = b_s3;                                                     \
        float a_t1 = __shfl_up_sync(FULL, a_T, 1, 16);                        \
        float b_t1 = __shfl_up_sync(FULL, b_T, 1, 16);                        \
        c0.PRE01 = fma2(c0.tI2M01, c0.FI01, mul2(c0.tM2M01, c0.FM01));        \
        c0.PRE23 = fma2(c0.tI2M23, c0.FI23, mul2(c0.tM2M23, c0.FM23));        \
        a_T = fmaf(mk1, a_t1, a_T);                                           \
        float a_t2 = __shfl_up_sync(FULL, a_T, 2, 16);                        \
        c1.PRE01 = fma2(c1.tI2M01, c1.FI01, mul2(c1.tM2M01, c1.FM01));        \
        c1.PRE23 = fma2(c1.tI2M23, c1.FI23, mul2(c1.tM2M23, c1.FM23));        \
        b_T = fmaf(mk1, b_t1, b_T);                                           \
        float b_t2 = __shfl_up_sync(FULL, b_T, 2, 16);                        \
        a_T = fmaf(mk2, a_t2, a_T);                                           \
        float a_t4 = __shfl_up_sync(FULL, a_T, 4, 16);                        \
        b_T = fmaf(mk2, b_t2, b_T);                                           \
        float b_t4 = __shfl_up_sync(FULL, b_T, 4, 16);                        \
        a_T = fmaf(mk4, a_t4, a_T);                                           \
        float a_t8 = __shfl_up_sync(FULL, a_T, 8, 16);                        \
        b_T = fmaf(mk4, b_t4, b_T);                                           \
        float b_t8 = __shfl_up_sync(FULL, b_T, 8, 16);                        \
        a_T = fmaf(mk8, a_t8, a_T);                                           \
        c0.incl = a_T;                                                        \
        float a_ex = a_T - a_s3;                                              \
        c0.w01 = pk(a_ex, a_ex + a_s0);                                       \
        c0.w23 = pk(a_ex + a_s1, a_ex + a_s2);                                \
        b_T = fmaf(mk8, b_t8, b_T);                                           \
        c1.incl = b_T;                                                        \
        float b_ex = b_T - b_s3;                                              \
        c1.w01 = pk(b_ex, b_ex + b_s0);                                       \
        c1.w23 = pk(b_ex + b_s1, b_ex + b_s2);                                \
    }

#define RESCALE(c)                                                            \
    {                                                                         \
        float m = fmaxf(fmaxf(lo2(c.FM01), hi2(c.FM01)),                      \
                        fmaxf(lo2(c.FM23), hi2(c.FM23)));                     \
        m = fmaxf(m, fmaxf(fmaxf(lo2(c.FI01), hi2(c.FI01)),                   \
                           fmaxf(lo2(c.FI23), hi2(c.FI23))));                 \
        m = fmaxf(m, fmaxf(c.FM64, c.FI64));                                  \
        _Pragma("unroll")                                                     \
        for (int off = 1; off < 16; off <<= 1)                                \
            m = fmaxf(m, __shfl_xor_sync(FULL, m, off, 16));                  \
        m = fmaxf(m, 1e-30f);                                                 \
        float r = 1.0f / m;                                                   \
        c.S += __logf(m);                                                     \
        u64 rr = pk(r, r);                                                    \
        c.FM01 = mul2(c.FM01, rr); c.FM23 = mul2(c.FM23, rr);                 \
        c.FI01 = mul2(c.FI01, rr); c.FI23 = mul2(c.FI23, rr);                 \
        c.w01 = mul2(c.w01, rr);   c.w23 = mul2(c.w23, rr);                   \
        c.PRE01 = mul2(c.PRE01, rr); c.PRE23 = mul2(c.PRE23, rr);             \
        c.FM64 *= r; c.FI64 *= r; c.incl *= r;                                \
    }

    DCHAIN(c0);
    c0.PRE01 = fma2(c0.tI2M01, c0.FI01, mul2(c0.tM2M01, c0.FM01));
    c0.PRE23 = fma2(c0.tI2M23, c0.FI23, mul2(c0.tM2M23, c0.FM23));
    DCHAIN(c1);
    c1.PRE01 = fma2(c1.tI2M01, c1.FI01, mul2(c1.tM2M01, c1.FM01));
    c1.PRE23 = fma2(c1.tI2M23, c1.FI23, mul2(c1.tM2M23, c1.FM23));

    #pragma unroll 1
    for (int lq = 0; lq < 16; lq++) {
        int4 xa0 = *(const int4*)&c0.sxw[8 * lq];
        int4 xa1 = *(const int4*)&c1.sxw[8 * lq];
        int4 xb0 = *(const int4*)&c0.sxw[8 * lq + 4];
        int4 xb1 = *(const int4*)&c1.sxw[8 * lq + 4];
        STEP2(xa0.x, xa1.x);
        STEP2(xa0.y, xa1.y);
        STEP2(xa0.z, xa1.z);
        STEP2(xa0.w, xa1.w);
        STEP2(xb0.x, xb1.x);
        STEP2(xb0.y, xb1.y);
        STEP2(xb0.z, xb1.z);
        STEP2(xb0.w, xb1.w);
        RESCALE(c0);
        RESCALE(c1);
    }

    #pragma unroll
    for (int ctx = 0; ctx < 2; ctx++) {
        Ctx& c = ctx ? c1 : c0;
        const int b = blockIdx.x * 16 + warp * 4 + ctx * 2 + seg;
        float fdTop = c.P_B * c.incl;
        float Pfin = fmaf(c.t64D2M, fdTop,
                          fmaf(c.t64I2M, c.FI64, c.t64M2M * c.FM64));
        float loss = -(c.S + __logf(Pfin));

        float kt;
        {
            float mu = mus[b * 16 + sl];
            float lv = logvars[b * 16 + sl];
            kt = 1.0f + lv - mu * mu - __expf(lv);
        }
        #pragma unroll
        for (int off = 1; off < 16; off <<= 1)
            kt += __shfl_xor_sync(FULL, kt, off, 16);

        if (sl == 15) sred[warp * 4 + ctx * 2 + seg] = loss - 0.5f * kt;
    }
    __syncthreads();
    if (threadIdx.x == 0) {
        float v = 0.0f;
        #pragma unroll
        for (int i = 0; i < 16; i++) v += sred[i];
        g_partials[blockIdx.x] = v;
        __threadfence();
        unsigned t = atomicAdd(&g_cnt, 1u);
        sflag = (t == gridDim.x - 1) ? 1 : 0;
    }
    __syncthreads();
    if (sflag) {
        float s = __ldcg(&g_partials[threadIdx.x])
                + __ldcg(&g_partials[threadIdx.x + 128]);
        s2[threadIdx.x] = s;
        __syncthreads();
        #pragma unroll
        for (int st = 64; st; st >>= 1) {
            if (threadIdx.x < st) s2[threadIdx.x] += s2[threadIdx.x + st];
            __syncthreads();
        }
        if (threadIdx.x == 0) {
            out[0] = s2[0] * (1.0f / 4096.0f);
            g_cnt = 0;
        }
    }
#undef STEP2
#undef DCHAIN
#undef RESCALE
}

extern "C" void kernel_launch(void* const* d_in, const int* in_sizes, int n_in,
                              void* d_out, int out_size) {
    const int*   x  = (const int*)d_in[0];
    const float* a  = (const float*)d_in[1];
    const float* e  = (const float*)d_in[2];
    const float* mu = (const float*)d_in[3];
    const float* lv = (const float*)d_in[4];
    const int B = in_sizes[0] / 128;          // 4096
    phmm_kernel<<<B / 16, 128>>>(x, a, e, mu, lv, (float*)d_out);
}

// round 16
// speedup vs baseline: 1.1691x; 1.1691x over previous
#include <cuda_runtime.h>

#define FULL 0xFFFFFFFFu
typedef unsigned long long u64;

// Per-block partials + completion counter (static device scratch).
__device__ float g_partials[512];
__device__ unsigned int g_cnt = 0;

// ---- f32x2 packed helpers (sm_100+ PTX) ----
__device__ __forceinline__ u64 pk(float lo, float hi) {
    u64 d; asm("mov.b64 %0, {%1, %2};" : "=l"(d) : "f"(lo), "f"(hi)); return d;
}
__device__ __forceinline__ float lo2(u64 d) { return __uint_as_float((unsigned)d); }
__device__ __forceinline__ float hi2(u64 d) { return __uint_as_float((unsigned)(d >> 32)); }
__device__ __forceinline__ u64 fma2(u64 a, u64 b, u64 c) {
    u64 d; asm("fma.rn.f32x2 %0, %1, %2, %3;" : "=l"(d) : "l"(a), "l"(b), "l"(c)); return d;
}
__device__ __forceinline__ u64 mul2(u64 a, u64 b) {
    u64 d; asm("mul.rn.f32x2 %0, %1, %2;" : "=l"(d) : "l"(a), "l"(b)); return d;
}

// Two batch elements per warp (16-lane segments), 4 states/lane packed in f32x2
// pairs. Linear-space scaled forward algorithm; D-chain via constant prefix
// products folded into consumers; single 16-wide segmented additive scan
// (4 shfl stages) per timestep. Best-measured configuration (R5: 32.8us).
__global__ void __launch_bounds__(128)
phmm_kernel(const int* __restrict__ xin,       // (B,128) int32 in [0,4)
            const float* __restrict__ trans,   // (B,65,7)
            const float* __restrict__ emis,    // (B,64,4)
            const float* __restrict__ mus,     // (B,16)
            const float* __restrict__ logvars, // (B,16)
            float* __restrict__ out)           // scalar
{
    const int lane = threadIdx.x & 31;
    const int sl   = lane & 15;            // lane within segment
    const int seg  = lane >> 4;            // which batch of this warp
    const int warp = threadIdx.x >> 5;
    const int b = blockIdx.x * 8 + warp * 2 + seg;

    __shared__ float4 sE4[4 * 4 * 32];     // [warp][sym][lane] emission quads
    __shared__ float  sEC[4 * 4 * 32];     // e[63] replicated
    __shared__ int    sx[8 * 132];         // symbols, stride de-conflicts
    __shared__ float  sred[8];
    __shared__ int    sflag;
    __shared__ float  s2[128];

    int* sxw = &sx[(warp * 2 + seg) * 132];
    {
        const int* xb = xin + b * 128;
        #pragma unroll
        for (int i = 0; i < 8; i++) sxw[sl + 16 * i] = xb[sl + 16 * i];
    }

    // ---- transitions (order M2M,M2I,M2D,I2M,I2I,D2M,D2D), rows 4sl..4sl+3 ----
    const float* ab = trans + b * 455;
    const float* a0 = ab + 28 * sl;
    float tM2M[4], tqM2I[4], tI2M[4], tqI2I[4], tM2D[4], tD2M[4], tD2D[4];
    #pragma unroll
    for (int j = 0; j < 4; j++) {
        tM2M[j]  = __expf(a0[7 * j + 0]);
        tqM2I[j] = 0.25f * __expf(a0[7 * j + 1]);   // LOG_Q folded
        tM2D[j]  = __expf(a0[7 * j + 2]);
        tI2M[j]  = __expf(a0[7 * j + 3]);
        tqI2I[j] = 0.25f * __expf(a0[7 * j + 4]);
        tD2M[j]  = __expf(a0[7 * j + 5]);
        tD2D[j]  = __expf(a0[7 * j + 6]);
    }
    const float* a64 = ab + 64 * 7;
    float t64M2M  = __expf(a64[0]);
    float tq64M2I = 0.25f * __expf(a64[1]);
    float t64I2M  = __expf(a64[3]);
    float tq64I2I = 0.25f * __expf(a64[4]);
    float t64D2M  = __expf(a64[5]);

    // ---- emission LUTs ----
    const float* eb = emis + b * 256;
    {
        #pragma unroll
        for (int x = 0; x < 4; x++) {
            float4 v;
            v.x = (sl == 0) ? 0.0f : __expf(eb[(4 * sl - 1) * 4 + x]);
            v.y = __expf(eb[(4 * sl + 0) * 4 + x]);
            v.z = __expf(eb[(4 * sl + 1) * 4 + x]);
            v.w = __expf(eb[(4 * sl + 2) * 4 + x]);
            sE4[(warp * 4 + x) * 32 + lane] = v;
            sEC[(warp * 4 + x) * 32 + lane] = __expf(eb[63 * 4 + x]);
        }
    }
    __syncwarp();

    // ---- prefix products of D-chain coefficients (constant in time) ----
    float P_B;
    u64 cc01, cc23, dd01, dd23;
    {
        float q0 = tD2D[0], q01 = q0 * tD2D[1], q012 = q01 * tD2D[2], q0123 = q012 * tD2D[3];
        float Q = q0123;
        #pragma unroll
        for (int off = 1; off < 16; off <<= 1) {
            float q = __shfl_up_sync(FULL, Q, off, 16);
            if (sl >= off) Q *= q;
        }
        float Pex = __shfl_up_sync(FULL, Q, 1, 16);   // P[4sl]
        if (sl == 0) Pex = 1.0f;
        float Pa = Pex * q0, Pb = Pex * q01, Pc = Pex * q012, Pd = Pex * q0123;
        dd01 = pk(tD2M[0] * Pex, tD2M[1] * Pa);
        dd23 = pk(tD2M[2] * Pb,  tD2M[3] * Pc);
        cc01 = pk(__fdividef(tM2D[0], Pa), __fdividef(tM2D[1], Pb));
        cc23 = pk(__fdividef(tM2D[2], Pc), __fdividef(tM2D[3], Pd));
        P_B = Q;                            // on sl=15: P[64]
    }
    const u64 tM2M01  = pk(tM2M[0], tM2M[1]),   tM2M23  = pk(tM2M[2], tM2M[3]);
    const u64 tI2M01  = pk(tI2M[0], tI2M[1]),   tI2M23  = pk(tI2M[2], tI2M[3]);
    const u64 tqI2I01 = pk(tqI2I[0], tqI2I[1]), tqI2I23 = pk(tqI2I[2], tqI2I[3]);
    const u64 tqM2I01 = pk(tqM2I[0], tqM2I[1]), tqM2I23 = pk(tqM2I[2], tqM2I[3]);

    // ---- init states ----
    u64 FM01 = pk((sl == 0) ? 1.0f : 0.0f, 0.0f), FM23 = pk(0.0f, 0.0f);
    u64 FI01 = pk(0.0f, 0.0f), FI23 = pk(0.0f, 0.0f);
    float FM64 = 0.0f, FI64 = 0.0f;
    u64 w01, w23, PRE01, PRE23;
    float incl, S = 0.0f;

    unsigned sE4a = (unsigned)__cvta_generic_to_shared(&sE4[warp * 128 + lane]);
    const float* sECw = &sEC[warp * 128 + lane];

    // D-chain: fD[k] = P[k]*prefixsum(u), u = cc*FM.
#define DCHAIN()                                                              \
    {                                                                         \
        u64 u01 = mul2(cc01, FM01);                                           \
        u64 u23 = mul2(cc23, FM23);                                           \
        float u0 = lo2(u01), u1 = hi2(u01), u2 = lo2(u23), u3 = hi2(u23);     \
        float s0 = u0, s1 = s0 + u1, s2 = s1 + u2, s3 = s2 + u3;              \
        float T = s3;                                                         \
        _Pragma("unroll")                                                     \
        for (int off = 1; off < 16; off <<= 1) {                              \
            float t = __shfl_up_sync(FULL, T, off, 16);                       \
            if (sl >= off) T += t;                                            \
        }                                                                     \
        incl = T;                                                             \
        float ex = T - s3;                                                    \
        w01 = pk(ex, ex + s0);                                                \
        w23 = pk(ex + s1, ex + s2);                                           \
    }

#define STEP(XS)                                                              \
    {                                                                         \
        u64 ev01, ev23;                                                       \
        asm("ld.shared.v2.u64 {%0, %1}, [%2];"                                \
            : "=l"(ev01), "=l"(ev23) : "r"(sE4a + (unsigned)(XS) * 512));     \
        float eC = sECw[(XS) * 32];                                           \
        u64 p01 = fma2(dd01, w01, PRE01);                                     \
        u64 p23 = fma2(dd23, w23, PRE23);                                     \
        float p3 = hi2(p23);                                                  \
        float pUp = __shfl_up_sync(FULL, p3, 1, 16);                          \
        FI01 = fma2(tqI2I01, FI01, mul2(tqM2I01, FM01));  /* OLD FM */        \
        FI23 = fma2(tqI2I23, FI23, mul2(tqM2I23, FM23));                      \
        FI64 = fmaf(tq64I2I, FI64, tq64M2I * FM64);                           \
        FM01 = mul2(ev01, pk(pUp, lo2(p01)));  /* sl0: ev.x==0 */             \
        FM23 = mul2(ev23, pk(hi2(p01), lo2(p23)));                            \
        FM64 = eC * p3;                        /* valid on sl=15 */           \
        DCHAIN();                                                             \
        PRE01 = fma2(tI2M01, FI01, mul2(tM2M01, FM01));                       \
        PRE23 = fma2(tI2M23, FI23, mul2(tM2M23, FM23));                       \
    }

    DCHAIN();   // from initial fM
    PRE01 = fma2(tI2M01, FI01, mul2(tM2M01, FM01));
    PRE23 = fma2(tI2M23, FI23, mul2(tM2M23, FM23));

    #pragma unroll 1
    for (int lq = 0; lq < 16; lq++) {
        int4 xa = *(const int4*)&sxw[8 * lq];
        int4 xb4 = *(const int4*)&sxw[8 * lq + 4];
        STEP(xa.x); STEP(xa.y); STEP(xa.z); STEP(xa.w);
        STEP(xb4.x); STEP(xb4.y); STEP(xb4.z); STEP(xb4.w);
        // rescale by segment max
        float m = fmaxf(fmaxf(lo2(FM01), hi2(FM01)), fmaxf(lo2(FM23), hi2(FM23)));
        m = fmaxf(m, fmaxf(fmaxf(lo2(FI01), hi2(FI01)), fmaxf(lo2(FI23), hi2(FI23))));
        m = fmaxf(m, fmaxf(FM64, FI64));
        #pragma unroll
        for (int off = 1; off < 16; off <<= 1)
            m = fmaxf(m, __shfl_xor_sync(FULL, m, off, 16));
        m = fmaxf(m, 1e-30f);
        float r = 1.0f / m;
        S += __logf(m);
        u64 rr = pk(r, r);
        FM01 = mul2(FM01, rr); FM23 = mul2(FM23, rr);
        FI01 = mul2(FI01, rr); FI23 = mul2(FI23, rr);
        w01 = mul2(w01, rr);   w23 = mul2(w23, rr);
        PRE01 = mul2(PRE01, rr); PRE23 = mul2(PRE23, rr);  // linear in states
        FM64 *= r; FI64 *= r; incl *= r;
    }

    // ---- final: three end transitions (sl=15 holds state 64 & full prefix) ----
    float fdTop = P_B * incl;
    float Pfin = fmaf(t64D2M, fdTop, fmaf(t64I2M, FI64, t64M2M * FM64));
    float loss = -(S + __logf(Pfin));             // valid on sl=15

    // ---- KLD: 16 segment lanes, one latent dim each ----
    float kt;
    {
        float mu = mus[b * 16 + sl];
        float lv = logvars[b * 16 + sl];
        kt = 1.0f + lv - mu * mu - __expf(lv);
    }
    #pragma unroll
    for (int off = 1; off < 16; off <<= 1)
        kt += __shfl_xor_sync(FULL, kt, off, 16);

    if (sl == 15) sred[warp * 2 + seg] = loss - 0.5f * kt;
    __syncthreads();
    if (threadIdx.x == 0) {
        float v = ((sred[0] + sred[1]) + (sred[2] + sred[3]))
                + ((sred[4] + sred[5]) + (sred[6] + sred[7]));
        g_partials[blockIdx.x] = v;
        __threadfence();
        unsigned t = atomicAdd(&g_cnt, 1u);
        sflag = (t == gridDim.x - 1) ? 1 : 0;
    }
    __syncthreads();
    if (sflag) {
        float s = 0.0f;
        #pragma unroll
        for (int i = 0; i < 4; i++)
            s += __ldcg(&g_partials[threadIdx.x + 128 * i]);
        s2[threadIdx.x] = s;
        __syncthreads();
        #pragma unroll
        for (int st = 64; st; st >>= 1) {
            if (threadIdx.x < st) s2[threadIdx.x] += s2[threadIdx.x + st];
            __syncthreads();
        }
        if (threadIdx.x == 0) {
            out[0] = s2[0] * (1.0f / 4096.0f);
            g_cnt = 0;  // self-reset for graph replay
        }
    }
#undef STEP
#undef DCHAIN
}

extern "C" void kernel_launch(void* const* d_in, const int* in_sizes, int n_in,
                              void* d_out, int out_size) {
    const int*   x  = (const int*)d_in[0];    // batch_input (B,128)
    const float* a  = (const float*)d_in[1];  // transition_probs (B,65,7)
    const float* e  = (const float*)d_in[2];  // emission_probs (B,64,4)
    const float* mu = (const float*)d_in[3];  // mus (B,16)
    const float* lv = (const float*)d_in[4];  // logvars (B,16)
    const int B = in_sizes[0] / 128;          // 4096
    phmm_kernel<<<B / 8, 128>>>(x, a, e, mu, lv, (float*)d_out);
}

// round 17
// speedup vs baseline: 1.1769x; 1.0067x over previous
#include <cuda_runtime.h>

#define FULL 0xFFFFFFFFu
typedef unsigned long long u64;

// Per-block partials + completion counter (static device scratch).
__device__ float g_partials[512];
__device__ unsigned int g_cnt = 0;

// ---- f32x2 packed helpers (sm_100+ PTX) ----
__device__ __forceinline__ u64 pk(float lo, float hi) {
    u64 d; asm("mov.b64 %0, {%1, %2};" : "=l"(d) : "f"(lo), "f"(hi)); return d;
}
__device__ __forceinline__ float lo2(u64 d) { return __uint_as_float((unsigned)d); }
__device__ __forceinline__ float hi2(u64 d) { return __uint_as_float((unsigned)(d >> 32)); }
__device__ __forceinline__ u64 fma2(u64 a, u64 b, u64 c) {
    u64 d; asm("fma.rn.f32x2 %0, %1, %2, %3;" : "=l"(d) : "l"(a), "l"(b), "l"(c)); return d;
}
__device__ __forceinline__ u64 mul2(u64 a, u64 b) {
    u64 d; asm("mul.rn.f32x2 %0, %1, %2;" : "=l"(d) : "l"(a), "l"(b)); return d;
}
__device__ __forceinline__ u64 add2(u64 a, u64 b) {
    u64 d; asm("add.rn.f32x2 %0, %1, %2;" : "=l"(d) : "l"(a), "l"(b)); return d;
}

// Two batch elements per warp (16-lane segments), 4 states/lane packed in two
// f32x2 pairs. Linear-space scaled forward; D-chain via constant prefix
// products folded into consumers; 16-wide segmented additive scan (4 stages).
__global__ void __launch_bounds__(128)
phmm_kernel(const int* __restrict__ xin,       // (B,128) int32 in [0,4)
            const float* __restrict__ trans,   // (B,65,7)
            const float* __restrict__ emis,    // (B,64,4)
            const float* __restrict__ mus,     // (B,16)
            const float* __restrict__ logvars, // (B,16)
            float* __restrict__ out)           // scalar
{
    const int lane = threadIdx.x & 31;
    const int sl   = lane & 15;            // lane within segment
    const int seg  = lane >> 4;            // which batch of this warp
    const int warp = threadIdx.x >> 5;
    const int b = blockIdx.x * 8 + warp * 2 + seg;

    __shared__ float4 sE4[4 * 4 * 32];     // [warp][sym][lane] emission quads
    __shared__ float  sEC[4 * 4 * 32];     // e[63] replicated
    __shared__ int    sx[8 * 132];         // symbols, stride de-conflicts
    __shared__ float  sred[8];
    __shared__ int    sflag;
    __shared__ float  s2[128];

    int* sxw = &sx[(warp * 2 + seg) * 132];
    {
        const int* xb = xin + b * 128;
        #pragma unroll
        for (int i = 0; i < 8; i++) sxw[sl + 16 * i] = xb[sl + 16 * i];
    }

    // ---- transitions (order M2M,M2I,M2D,I2M,I2I,D2M,D2D), rows 4sl..4sl+3 ----
    const float* ab = trans + b * 455;
    const float* a0 = ab + 28 * sl;
    float tM2M[4], tqM2I[4], tI2M[4], tqI2I[4], tM2D[4], tD2M[4], tD2D[4];
    #pragma unroll
    for (int j = 0; j < 4; j++) {
        tM2M[j]  = __expf(a0[7 * j + 0]);
        tqM2I[j] = 0.25f * __expf(a0[7 * j + 1]);   // LOG_Q folded
        tM2D[j]  = __expf(a0[7 * j + 2]);
        tI2M[j]  = __expf(a0[7 * j + 3]);
        tqI2I[j] = 0.25f * __expf(a0[7 * j + 4]);
        tD2M[j]  = __expf(a0[7 * j + 5]);
        tD2D[j]  = __expf(a0[7 * j + 6]);
    }
    const float* a64 = ab + 64 * 7;
    float t64M2M  = __expf(a64[0]);
    float tq64M2I = 0.25f * __expf(a64[1]);
    float t64I2M  = __expf(a64[3]);
    float tq64I2I = 0.25f * __expf(a64[4]);
    float t64D2M  = __expf(a64[5]);

    // ---- emission LUTs ----
    const float* eb = emis + b * 256;
    {
        #pragma unroll
        for (int x = 0; x < 4; x++) {
            float4 v;
            v.x = (sl == 0) ? 0.0f : __expf(eb[(4 * sl - 1) * 4 + x]);
            v.y = __expf(eb[(4 * sl + 0) * 4 + x]);
            v.z = __expf(eb[(4 * sl + 1) * 4 + x]);
            v.w = __expf(eb[(4 * sl + 2) * 4 + x]);
            sE4[(warp * 4 + x) * 32 + lane] = v;
            sEC[(warp * 4 + x) * 32 + lane] = __expf(eb[63 * 4 + x]);
        }
    }
    __syncwarp();

    // ---- prefix products of D-chain coefficients (constant in time) ----
    float P64fac, cc0v, cc1v, cc2v, cc3v;
    u64 dd01, dd23;
    {
        float q0 = tD2D[0], q01 = q0 * tD2D[1], q012 = q01 * tD2D[2], q0123 = q012 * tD2D[3];
        float Q = q0123;
        #pragma unroll
        for (int off = 1; off < 16; off <<= 1) {
            float q = __shfl_up_sync(FULL, Q, off, 16);
            if (sl >= off) Q *= q;
        }
        float Pex = __shfl_up_sync(FULL, Q, 1, 16);   // P[4sl]
        if (sl == 0) Pex = 1.0f;
        float Pa = Pex * q0, Pb = Pex * q01, Pc = Pex * q012, Pd = Pex * q0123;
        dd01 = pk(tD2M[0] * Pex, tD2M[1] * Pa);
        dd23 = pk(tD2M[2] * Pb,  tD2M[3] * Pc);
        cc0v = __fdividef(tM2D[0], Pa);
        cc1v = __fdividef(tM2D[1], Pb);
        cc2v = __fdividef(tM2D[2], Pc);
        cc3v = __fdividef(tM2D[3], Pd);
        P64fac = Pd;                        // on sl=15: P[64]
    }
    const u64 cc01 = pk(cc0v, cc1v), cc23 = pk(cc2v, cc3v);
    const u64 tM2M01  = pk(tM2M[0], tM2M[1]),   tM2M23  = pk(tM2M[2], tM2M[3]);
    const u64 tI2M01  = pk(tI2M[0], tI2M[1]),   tI2M23  = pk(tI2M[2], tI2M[3]);
    const u64 tqI2I01 = pk(tqI2I[0], tqI2I[1]), tqI2I23 = pk(tqI2I[2], tqI2I[3]);
    const u64 tqM2I01 = pk(tqM2I[0], tqM2I[1]), tqM2I23 = pk(tqM2I[2], tqM2I[3]);

    // ---- init states ----
    u64 FM01 = pk((sl == 0) ? 1.0f : 0.0f, 0.0f), FM23 = pk(0.0f, 0.0f);
    u64 FI01 = pk(0.0f, 0.0f), FI23 = pk(0.0f, 0.0f);
    float FM64 = 0.0f, FI64 = 0.0f;
    u64 w01, w23;
    float incl, S = 0.0f;

    unsigned sE4a = (unsigned)__cvta_generic_to_shared(&sE4[warp * 128 + lane]);
    const float* sECw = &sEC[warp * 128 + lane];

#define DCHAIN()                                                              \
    {                                                                         \
        u64 u01 = mul2(cc01, FM01);                                           \
        u64 u23 = mul2(cc23, FM23);                                           \
        float u0 = lo2(u01), u1 = hi2(u01), u2 = lo2(u23), u3 = hi2(u23);     \
        float s0 = u0, s1 = s0 + u1, s2 = s1 + u2, s3 = s2 + u3;              \
        float T = s3;                                                         \
        _Pragma("unroll")                                                     \
        for (int off = 1; off < 16; off <<= 1) {                              \
            float t = __shfl_up_sync(FULL, T, off, 16);                       \
            if (sl >= off) T += t;                                            \
        }                                                                     \
        incl = T;                                                             \
        float ex = T - s3;                                                    \
        w01 = pk(ex, ex + s0);                                                \
        w23 = pk(ex + s1, ex + s2);                                           \
    }

#define STEP(XS)                                                              \
    {                                                                         \
        u64 ev01, ev23;                                                       \
        asm("ld.shared.v2.u64 {%0, %1}, [%2];"                                \
            : "=l"(ev01), "=l"(ev23) : "r"(sE4a + (unsigned)(XS) * 512));     \
        float eC = sECw[(XS) * 32];                                           \
        u64 p01 = fma2(dd01, w01, fma2(tI2M01, FI01, mul2(tM2M01, FM01)));    \
        u64 p23 = fma2(dd23, w23, fma2(tI2M23, FI23, mul2(tM2M23, FM23)));    \
        float p3 = hi2(p23);                                                  \
        float pUp = __shfl_up_sync(FULL, p3, 1, 16);                          \
        FI01 = fma2(tqI2I01, FI01, mul2(tqM2I01, FM01));  /* uses OLD FM */   \
        FI23 = fma2(tqI2I23, FI23, mul2(tqM2I23, FM23));                      \
        FI64 = fmaf(tq64I2I, FI64, tq64M2I * FM64);                           \
        FM01 = mul2(ev01, pk(pUp, lo2(p01)));  /* sl0: ev.x==0 */             \
        FM23 = mul2(ev23, pk(hi2(p01), lo2(p23)));                            \
        FM64 = eC * p3;                     /* valid on sl=15 */              \
        DCHAIN();                                                             \
    }

    DCHAIN();  // from initial fM

    #pragma unroll 1
    for (int lq = 0; lq < 16; lq++) {
        int4 xa = *(const int4*)&sxw[8 * lq];
        int4 xb4 = *(const int4*)&sxw[8 * lq + 4];
        STEP(xa.x); STEP(xa.y); STEP(xa.z); STEP(xa.w);
        STEP(xb4.x); STEP(xb4.y); STEP(xb4.z); STEP(xb4.w);
        // rescale by segment max (pair halves are plain regs at SASS level)
        float m = fmaxf(fmaxf(lo2(FM01), hi2(FM01)), fmaxf(lo2(FM23), hi2(FM23)));
        m = fmaxf(m, fmaxf(fmaxf(lo2(FI01), hi2(FI01)), fmaxf(lo2(FI23), hi2(FI23))));
        m = fmaxf(m, fmaxf(FM64, FI64));
        #pragma unroll
        for (int off = 1; off < 16; off <<= 1)
            m = fmaxf(m, __shfl_xor_sync(FULL, m, off, 16));
        m = fmaxf(m, 1e-30f);
        float r = 1.0f / m;
        S += __logf(m);
        u64 rr = pk(r, r);
        FM01 = mul2(FM01, rr); FM23 = mul2(FM23, rr);
        FI01 = mul2(FI01, rr); FI23 = mul2(FI23, rr);
        w01 = mul2(w01, rr);   w23 = mul2(w23, rr);
        FM64 *= r; FI64 *= r; incl *= r;
    }

    // ---- final: three end transitions (sl=15 holds state 64 & full prefix) ----
    float fdTop = P64fac * incl;
    float Pfin = fmaf(t64D2M, fdTop, fmaf(t64I2M, FI64, t64M2M * FM64));
    float loss = -(S + __logf(Pfin));             // valid on sl=15

    // ---- KLD: 16 segment lanes, one latent dim each ----
    float kt;
    {
        float mu = mus[b * 16 + sl];
        float lv = logvars[b * 16 + sl];
        kt = 1.0f + lv - mu * mu - __expf(lv);
    }
    #pragma unroll
    for (int off = 1; off < 16; off <<= 1)
        kt += __shfl_xor_sync(FULL, kt, off, 16);

    if (sl == 15) sred[warp * 2 + seg] = loss - 0.5f * kt;
    __syncthreads();
    if (threadIdx.x == 0) {
        float v = ((sred[0] + sred[1]) + (sred[2] + sred[3]))
                + ((sred[4] + sred[5]) + (sred[6] + sred[7]));
        g_partials[blockIdx.x] = v;
        __threadfence();
        unsigned t = atomicAdd(&g_cnt, 1u);
        sflag = (t == gridDim.x - 1) ? 1 : 0;
    }
    __syncthreads();
    if (sflag) {
        float s = 0.0f;
        #pragma unroll
        for (int i = 0; i < 4; i++)
            s += __ldcg(&g_partials[threadIdx.x + 128 * i]);
        s2[threadIdx.x] = s;
        __syncthreads();
        #pragma unroll
        for (int st = 64; st; st >>= 1) {
            if (threadIdx.x < st) s2[threadIdx.x] += s2[threadIdx.x + st];
            __syncthreads();
        }
        if (threadIdx.x == 0) {
            out[0] = s2[0] * (1.0f / 4096.0f);
            g_cnt = 0;  // self-reset for graph replay
        }
    }
#undef STEP
#undef DCHAIN
}

extern "C" void kernel_launch(void* const* d_in, const int* in_sizes, int n_in,
                              void* d_out, int out_size) {
    const int*   x  = (const int*)d_in[0];    // batch_input (B,128)
    const float* a  = (const float*)d_in[1];  // transition_probs (B,65,7)
    const float* e  = (const float*)d_in[2];  // emission_probs (B,64,4)
    const float* mu = (const float*)d_in[3];  // mus (B,16)
    const float* lv = (const float*)d_in[4];  // logvars (B,16)
    const int B = in_sizes[0] / 128;          // 4096
    phmm_kernel<<<B / 8, 128>>>(x, a, e, mu, lv, (float*)d_out);
}